// round 5
// baseline (speedup 1.0000x reference)
#include <cuda_runtime.h>
#include <cstdint>

#define N_NODES 50000
#define E_EDGES 800000
#define F 128

// Scratch (allocation-free rule: __device__ globals)
__device__ float g_agg[N_NODES * F];   // 25.6 MB, per-dst aggregated messages
__device__ float g_wt[F * F];          // W transposed: g_wt[k*F + c] = W[c*F + k]

// ---------------------------------------------------------------------------
// Kernel 1: zero the aggregation buffer + transpose W for coalesced GEMM loads
// ---------------------------------------------------------------------------
__global__ void prep_kernel(const float* __restrict__ W) {
    int tid = blockIdx.x * blockDim.x + threadIdx.x;
    if (tid < F * F) {
        int c = tid / F;
        int k = tid % F;
        g_wt[k * F + c] = W[c * F + k];
    }
    const int total4 = (N_NODES * F) / 4;
    float4 z = make_float4(0.f, 0.f, 0.f, 0.f);
    float4* a4 = reinterpret_cast<float4*>(g_agg);
    for (int i = tid; i < total4; i += gridDim.x * blockDim.x)
        a4[i] = z;
}

// ---------------------------------------------------------------------------
// Kernel 2: edge scatter. One warp per edge; lane l handles floats [4l,4l+4).
// agg[dst] += (w+1) * feature[src]  via vectorized L2 reduction (red.v4.f32).
// ---------------------------------------------------------------------------
__global__ __launch_bounds__(256) void edge_scatter_kernel(
    const float* __restrict__ feature,
    const float* __restrict__ weight,
    const int*   __restrict__ src,
    const int*   __restrict__ dst)
{
    int e    = (blockIdx.x * blockDim.x + threadIdx.x) >> 5;
    int lane = threadIdx.x & 31;
    if (e >= E_EDGES) return;

    int   s = __ldg(src + e);
    int   d = __ldg(dst + e);
    float w = __ldg(weight + e) + 1.0f;

    const float4* fs = reinterpret_cast<const float4*>(feature + (size_t)s * F);
    float4 v = fs[lane];
    v.x *= w; v.y *= w; v.z *= w; v.w *= w;

    float* p = g_agg + (size_t)d * F + lane * 4;
    asm volatile("red.global.add.v4.f32 [%0], {%1, %2, %3, %4};"
                 :: "l"(p), "f"(v.x), "f"(v.y), "f"(v.z), "f"(v.w)
                 : "memory");
}

// ---------------------------------------------------------------------------
// Kernel 3: out = (feature*(sw+1) + agg) @ W^T + b
// Tiled fp32 SIMT GEMM. Block: 256 threads, 64 output rows, full 128 cols.
// Per-thread tile: 4 rows x 8 cols. K processed in two chunks of 64.
// Shared: Ws[64][128] (32KB) + Hs[64][64] (16KB) = 48KB exactly.
// ---------------------------------------------------------------------------
__global__ __launch_bounds__(256) void gemm_kernel(
    const float* __restrict__ feature,
    const float* __restrict__ selfw,
    const float* __restrict__ bvec,
    float*       __restrict__ out)
{
    __shared__ float Ws[64 * F];    // [k][c]
    __shared__ float Hs[64 * 64];   // [k][row]

    const int tid = threadIdx.x;
    const int tx  = tid & 15;       // col group: cols tx*8 .. tx*8+7
    const int ty  = tid >> 4;       // row group: rows ty*4 .. ty*4+3 (0..15)
    const int Rbase = blockIdx.x * 64;

    // loader mapping: each thread fills one row-slice of Hs
    const int lrow = tid >> 2;      // 0..63
    const int lseg = tid & 3;       // k segment of 16
    const int grow  = Rbase + lrow;
    const int growc = grow < N_NODES ? grow : (N_NODES - 1);
    const float swv = __ldg(selfw + growc) + 1.0f;
    const float* frow = feature + (size_t)growc * F;
    const float* arow = g_agg  + (size_t)growc * F;

    float acc[4][8];
#pragma unroll
    for (int i = 0; i < 4; i++)
#pragma unroll
        for (int j = 0; j < 8; j++) acc[i][j] = 0.f;

#pragma unroll
    for (int kk = 0; kk < F; kk += 64) {
        if (kk) __syncthreads();

        // fill Ws: 8192 floats = 2048 float4, linear coalesced from g_wt
        {
            const float4* s4 = reinterpret_cast<const float4*>(g_wt + kk * F);
            float4*       d4 = reinterpret_cast<float4*>(Ws);
#pragma unroll
            for (int q = 0; q < 8; q++)
                d4[tid + q * 256] = s4[tid + q * 256];
        }
        // fill Hs: h = feature*(sw+1) + agg, stored transposed [k][row]
#pragma unroll
        for (int q = 0; q < 4; q++) {
            int k0 = lseg * 16 + q * 4;
            float4 f4 = *reinterpret_cast<const float4*>(frow + kk + k0);
            float4 a4 = *reinterpret_cast<const float4*>(arow + kk + k0);
            Hs[(k0 + 0) * 64 + lrow] = fmaf(f4.x, swv, a4.x);
            Hs[(k0 + 1) * 64 + lrow] = fmaf(f4.y, swv, a4.y);
            Hs[(k0 + 2) * 64 + lrow] = fmaf(f4.z, swv, a4.z);
            Hs[(k0 + 3) * 64 + lrow] = fmaf(f4.w, swv, a4.w);
        }
        __syncthreads();

#pragma unroll 8
        for (int k = 0; k < 64; k++) {
            float4 w0 = *reinterpret_cast<const float4*>(Ws + k * F + tx * 8);
            float4 w1 = *reinterpret_cast<const float4*>(Ws + k * F + tx * 8 + 4);
#pragma unroll
            for (int i = 0; i < 4; i++) {
                float h = Hs[k * 64 + ty * 4 + i];
                acc[i][0] = fmaf(h, w0.x, acc[i][0]);
                acc[i][1] = fmaf(h, w0.y, acc[i][1]);
                acc[i][2] = fmaf(h, w0.z, acc[i][2]);
                acc[i][3] = fmaf(h, w0.w, acc[i][3]);
                acc[i][4] = fmaf(h, w1.x, acc[i][4]);
                acc[i][5] = fmaf(h, w1.y, acc[i][5]);
                acc[i][6] = fmaf(h, w1.z, acc[i][6]);
                acc[i][7] = fmaf(h, w1.w, acc[i][7]);
            }
        }
    }

    // epilogue: add bias, store
    float4 b0 = *reinterpret_cast<const float4*>(bvec + tx * 8);
    float4 b1 = *reinterpret_cast<const float4*>(bvec + tx * 8 + 4);
#pragma unroll
    for (int i = 0; i < 4; i++) {
        int r = Rbase + ty * 4 + i;
        if (r < N_NODES) {
            float4 o0 = make_float4(acc[i][0] + b0.x, acc[i][1] + b0.y,
                                    acc[i][2] + b0.z, acc[i][3] + b0.w);
            float4 o1 = make_float4(acc[i][4] + b1.x, acc[i][5] + b1.y,
                                    acc[i][6] + b1.z, acc[i][7] + b1.w);
            *reinterpret_cast<float4*>(out + (size_t)r * F + tx * 8)     = o0;
            *reinterpret_cast<float4*>(out + (size_t)r * F + tx * 8 + 4) = o1;
        }
    }
}

// ---------------------------------------------------------------------------
// Launch: inputs in metadata order:
//   0 feature [N,128] f32   1 self_weight [N,1] f32   2 weight [E] f32
//   3 src [E] i32           4 dst [E] i32
//   5 W [128,128] f32       6 b [128] f32
// Output: [N,128] f32
// ---------------------------------------------------------------------------
extern "C" void kernel_launch(void* const* d_in, const int* in_sizes, int n_in,
                              void* d_out, int out_size)
{
    const float* feature = (const float*)d_in[0];
    const float* selfw   = (const float*)d_in[1];
    const float* weight  = (const float*)d_in[2];
    const int*   src     = (const int*)d_in[3];
    const int*   dst     = (const int*)d_in[4];
    const float* W       = (const float*)d_in[5];
    const float* bvec    = (const float*)d_in[6];
    float*       out     = (float*)d_out;

    // 1) zero agg + transpose W
    prep_kernel<<<2048, 256>>>(W);

    // 2) edge scatter: one warp per edge, 8 warps per block
    const int edge_blocks = (E_EDGES + 7) / 8;     // 100000
    edge_scatter_kernel<<<edge_blocks, 256>>>(feature, weight, src, dst);

    // 3) fused affine + GEMM + bias
    const int gemm_blocks = (N_NODES + 63) / 64;   // 782
    gemm_kernel<<<gemm_blocks, 256>>>(feature, selfw, bvec, out);
}

// round 6
// speedup vs baseline: 1.2940x; 1.2940x over previous
#include <cuda_runtime.h>
#include <cstdint>

#define N_NODES 50000
#define E_EDGES 800000
#define F 128
#define NB_SCAN 196              // ceil(50000/256)
#define HS_STRIDE 132            // 128 + 4 pad (bank-conflict-free Hs reads)

// ---- scratch (__device__ globals; allocation-free rule) ----
__device__ int   g_cnt[50176];     // per-node in-degree
__device__ int   g_start[50176];   // CSR offsets
__device__ int   g_cursor[50176];  // atomic fill cursors
__device__ int   g_bsum[256];      // per-scan-block sums
__device__ int   g_boff[256];      // exclusive scan of block sums
__device__ int2  g_ebuf[E_EDGES];  // bucketed edges: {src, bits(w+1)}
__device__ float g_wt[F * F];      // W transposed: g_wt[k*F+c] = W[c*F+k]

// ---------------------------------------------------------------------------
// K1: zero counters + transpose W
// ---------------------------------------------------------------------------
__global__ void prep_kernel(const float* __restrict__ W) {
    int tid = blockIdx.x * blockDim.x + threadIdx.x;
    if (tid < F * F) {
        int c = tid / F, k = tid % F;
        g_wt[k * F + c] = W[c * F + k];
    }
    for (int i = tid; i < 50176; i += gridDim.x * blockDim.x)
        g_cnt[i] = 0;
}

// ---------------------------------------------------------------------------
// K2: histogram of dst
// ---------------------------------------------------------------------------
__global__ __launch_bounds__(256) void hist_kernel(const int* __restrict__ dst) {
    int base = (blockIdx.x * blockDim.x + threadIdx.x) * 4;
#pragma unroll
    for (int q = 0; q < 4; q++) {
        int e = base + q;
        if (e < E_EDGES) atomicAdd(&g_cnt[__ldg(dst + e)], 1);
    }
}

// ---------------------------------------------------------------------------
// K3: per-block (256 nodes) sum of counts
// ---------------------------------------------------------------------------
__global__ __launch_bounds__(256) void bsum_kernel() {
    __shared__ int sh[256];
    int idx = blockIdx.x * 256 + threadIdx.x;
    int v = (idx < N_NODES) ? g_cnt[idx] : 0;
    sh[threadIdx.x] = v;
    __syncthreads();
    for (int s = 128; s > 0; s >>= 1) {
        if (threadIdx.x < s) sh[threadIdx.x] += sh[threadIdx.x + s];
        __syncthreads();
    }
    if (threadIdx.x == 0) g_bsum[blockIdx.x] = sh[0];
}

// ---------------------------------------------------------------------------
// K4: exclusive scan of the NB_SCAN block sums (single block)
// ---------------------------------------------------------------------------
__global__ __launch_bounds__(256) void bscan_kernel() {
    __shared__ int sh[256];
    int t = threadIdx.x;
    int v = (t < NB_SCAN) ? g_bsum[t] : 0;
    sh[t] = v;
    __syncthreads();
    // Hillis-Steele inclusive scan
    for (int d = 1; d < 256; d <<= 1) {
        int add = (t >= d) ? sh[t - d] : 0;
        __syncthreads();
        sh[t] += add;
        __syncthreads();
    }
    if (t < NB_SCAN) g_boff[t] = sh[t] - v;   // exclusive
}

// ---------------------------------------------------------------------------
// K5: per-node exclusive offsets = block_off + local exclusive scan
// ---------------------------------------------------------------------------
__global__ __launch_bounds__(256) void offsets_kernel() {
    __shared__ int sh[256];
    int t = threadIdx.x;
    int idx = blockIdx.x * 256 + t;
    int v = (idx < N_NODES) ? g_cnt[idx] : 0;
    sh[t] = v;
    __syncthreads();
    for (int d = 1; d < 256; d <<= 1) {
        int add = (t >= d) ? sh[t - d] : 0;
        __syncthreads();
        sh[t] += add;
        __syncthreads();
    }
    if (idx < N_NODES) {
        int start = g_boff[blockIdx.x] + sh[t] - v;
        g_start[idx]  = start;
        g_cursor[idx] = start;
    }
}

// ---------------------------------------------------------------------------
// K6: bucket edges by dst:  ebuf[pos] = {src, bits(weight+1)}
// ---------------------------------------------------------------------------
__global__ __launch_bounds__(256) void bucket_kernel(
    const float* __restrict__ weight,
    const int*   __restrict__ src,
    const int*   __restrict__ dst)
{
    int base = (blockIdx.x * blockDim.x + threadIdx.x) * 4;
#pragma unroll
    for (int q = 0; q < 4; q++) {
        int e = base + q;
        if (e < E_EDGES) {
            int d = __ldg(dst + e);
            int pos = atomicAdd(&g_cursor[d], 1);
            g_ebuf[pos] = make_int2(__ldg(src + e),
                                    __float_as_int(__ldg(weight + e) + 1.0f));
        }
    }
}

// ---------------------------------------------------------------------------
// K7: fused aggregate + affine + GEMM + bias.
//   Block = 256 threads, 64 output rows.
//   Phase A: warp w aggregates rows w*8..w*8+7 from its CSR edge lists
//            (registers, MLP=2), adds self term, writes h row to smem.
//   Phase B: fp32 tiled GEMM, Ws in 16-row k-chunks (fits 48KB static smem).
// ---------------------------------------------------------------------------
__global__ __launch_bounds__(256) void fused_kernel(
    const float* __restrict__ feature,
    const float* __restrict__ selfw,
    const float* __restrict__ bvec,
    float*       __restrict__ out)
{
    __shared__ float Hs[64 * HS_STRIDE];   // h rows  [row][k], padded
    __shared__ float Ws[16 * F];           // W^T chunk [k][c]

    const int tid  = threadIdx.x;
    const int lane = tid & 31;
    const int warp = tid >> 5;             // 0..7
    const int Rbase = blockIdx.x * 64;
    const float4* f4 = reinterpret_cast<const float4*>(feature);

    // ---------------- Phase A: aggregation ----------------
#pragma unroll 1
    for (int rr = 0; rr < 8; rr++) {
        int rloc = warp * 8 + rr;
        int r = Rbase + rloc;
        int rc = r < N_NODES ? r : (N_NODES - 1);
        int beg = __ldg(&g_start[rc]);
        int cnt = (r < N_NODES) ? __ldg(&g_cnt[rc]) : 0;
        int end = beg + cnt;

        float4 acc0 = make_float4(0.f, 0.f, 0.f, 0.f);
        float4 acc1 = make_float4(0.f, 0.f, 0.f, 0.f);

        int i = beg;
        for (; i + 2 <= end; i += 2) {
            int2 ea = g_ebuf[i];
            int2 eb = g_ebuf[i + 1];
            float4 va = __ldg(f4 + ea.x * 32 + lane);
            float4 vb = __ldg(f4 + eb.x * 32 + lane);
            float wa = __int_as_float(ea.y);
            float wb = __int_as_float(eb.y);
            acc0.x = fmaf(wa, va.x, acc0.x);
            acc0.y = fmaf(wa, va.y, acc0.y);
            acc0.z = fmaf(wa, va.z, acc0.z);
            acc0.w = fmaf(wa, va.w, acc0.w);
            acc1.x = fmaf(wb, vb.x, acc1.x);
            acc1.y = fmaf(wb, vb.y, acc1.y);
            acc1.z = fmaf(wb, vb.z, acc1.z);
            acc1.w = fmaf(wb, vb.w, acc1.w);
        }
        if (i < end) {
            int2 ea = g_ebuf[i];
            float4 va = __ldg(f4 + ea.x * 32 + lane);
            float wa = __int_as_float(ea.y);
            acc0.x = fmaf(wa, va.x, acc0.x);
            acc0.y = fmaf(wa, va.y, acc0.y);
            acc0.z = fmaf(wa, va.z, acc0.z);
            acc0.w = fmaf(wa, va.w, acc0.w);
        }

        float sw = __ldg(selfw + rc) + 1.0f;
        float4 fv = __ldg(f4 + rc * 32 + lane);
        float4 h;
        h.x = fmaf(fv.x, sw, acc0.x + acc1.x);
        h.y = fmaf(fv.y, sw, acc0.y + acc1.y);
        h.z = fmaf(fv.z, sw, acc0.z + acc1.z);
        h.w = fmaf(fv.w, sw, acc0.w + acc1.w);
        // coalesced, conflict-free float4 store of the h row
        *reinterpret_cast<float4*>(Hs + rloc * HS_STRIDE + lane * 4) = h;
    }
    __syncthreads();

    // ---------------- Phase B: GEMM ----------------
    const int tx = tid & 15;   // cols tx*8..tx*8+7
    const int ty = tid >> 4;   // rows ty*4..ty*4+3

    float acc[4][8];
#pragma unroll
    for (int i = 0; i < 4; i++)
#pragma unroll
        for (int j = 0; j < 8; j++) acc[i][j] = 0.f;

#pragma unroll 1
    for (int kk = 0; kk < F; kk += 16) {
        // load 16-row k-chunk of W^T: 512 float4 / 256 threads = 2 each
        {
            const float4* s4 = reinterpret_cast<const float4*>(g_wt + kk * F);
            float4*       d4 = reinterpret_cast<float4*>(Ws);
            d4[tid]       = s4[tid];
            d4[tid + 256] = s4[tid + 256];
        }
        __syncthreads();

#pragma unroll
        for (int k = 0; k < 16; k++) {
            float4 w0 = *reinterpret_cast<const float4*>(Ws + k * F + tx * 8);
            float4 w1 = *reinterpret_cast<const float4*>(Ws + k * F + tx * 8 + 4);
            int kg = kk + k;
#pragma unroll
            for (int i = 0; i < 4; i++) {
                float h = Hs[(ty * 4 + i) * HS_STRIDE + kg];
                acc[i][0] = fmaf(h, w0.x, acc[i][0]);
                acc[i][1] = fmaf(h, w0.y, acc[i][1]);
                acc[i][2] = fmaf(h, w0.z, acc[i][2]);
                acc[i][3] = fmaf(h, w0.w, acc[i][3]);
                acc[i][4] = fmaf(h, w1.x, acc[i][4]);
                acc[i][5] = fmaf(h, w1.y, acc[i][5]);
                acc[i][6] = fmaf(h, w1.z, acc[i][6]);
                acc[i][7] = fmaf(h, w1.w, acc[i][7]);
            }
        }
        __syncthreads();
    }

    // epilogue: bias + store
    float4 b0 = *reinterpret_cast<const float4*>(bvec + tx * 8);
    float4 b1 = *reinterpret_cast<const float4*>(bvec + tx * 8 + 4);
#pragma unroll
    for (int i = 0; i < 4; i++) {
        int r = Rbase + ty * 4 + i;
        if (r < N_NODES) {
            float4 o0 = make_float4(acc[i][0] + b0.x, acc[i][1] + b0.y,
                                    acc[i][2] + b0.z, acc[i][3] + b0.w);
            float4 o1 = make_float4(acc[i][4] + b1.x, acc[i][5] + b1.y,
                                    acc[i][6] + b1.z, acc[i][7] + b1.w);
            *reinterpret_cast<float4*>(out + (size_t)r * F + tx * 8)     = o0;
            *reinterpret_cast<float4*>(out + (size_t)r * F + tx * 8 + 4) = o1;
        }
    }
}

// ---------------------------------------------------------------------------
// Launch. Inputs (metadata order):
//   0 feature [N,128] f32   1 self_weight [N,1] f32   2 weight [E] f32
//   3 src [E] i32           4 dst [E] i32             5 W [128,128] f32
//   6 b [128] f32           Output: [N,128] f32
// ---------------------------------------------------------------------------
extern "C" void kernel_launch(void* const* d_in, const int* in_sizes, int n_in,
                              void* d_out, int out_size)
{
    const float* feature = (const float*)d_in[0];
    const float* selfw   = (const float*)d_in[1];
    const float* weight  = (const float*)d_in[2];
    const int*   src     = (const int*)d_in[3];
    const int*   dst     = (const int*)d_in[4];
    const float* W       = (const float*)d_in[5];
    const float* bvec    = (const float*)d_in[6];
    float*       out     = (float*)d_out;

    const int edge_blocks = (E_EDGES + 1023) / 1024;   // 782 (4 edges/thread)
    const int gemm_blocks = (N_NODES + 63) / 64;       // 782

    prep_kernel<<<256, 256>>>(W);                      // zero counts + W^T
    hist_kernel<<<edge_blocks, 256>>>(dst);            // in-degree histogram
    bsum_kernel<<<NB_SCAN, 256>>>();                   // block sums
    bscan_kernel<<<1, 256>>>();                        // scan block sums
    offsets_kernel<<<NB_SCAN, 256>>>();                // CSR offsets + cursors
    bucket_kernel<<<edge_blocks, 256>>>(weight, src, dst);  // counting sort
    fused_kernel<<<gemm_blocks, 256>>>(feature, selfw, bvec, out);
}